// round 1
// baseline (speedup 1.0000x reference)
#include <cuda_runtime.h>

#define NN 100000
#define EE 1600000
#define ET (EE + NN)
#define NB ((NN + 1023) / 1024)   // 98 scan blocks

// ---------------- scratch (device globals; no allocations) ----------------
__device__ __align__(16) float g_xh1[(size_t)NN * 256];  // layer1 x@W1
__device__ __align__(16) float g_h  [(size_t)NN * 256];  // layer1 output (post relu)
__device__ __align__(16) float g_xh2[(size_t)NN * 32];   // layer2 h@W2
__device__ float g_es1[NN * 8];
__device__ float g_ed1[NN * 8];
__device__ float g_es2[NN];
__device__ float g_ed2[NN];
__device__ int   g_deg[NN];
__device__ int   g_rowptr[NN + 1];
__device__ int   g_cursor[NN];
__device__ int   g_adj[ET];
__device__ int   g_bsums[NB];
__device__ int   g_is64;

// ---------------- int32/int64 edge_index handling ----------------
// JAX without x64 silently downgrades the requested int64 edge_index to int32.
// Detect at runtime: if dtype is int64 (little-endian, values < 2^31), every
// odd 32-bit word is a zero high-half. With int32 data those words are random
// node ids (P(all 256 are 0) ~ 0).
__global__ void k_detect(const int* __restrict__ ei) {
    if (threadIdx.x == 0) {
        int nz = 0;
        for (int i = 0; i < 256; i++) nz |= ei[2 * i + 1];
        g_is64 = (nz == 0) ? 1 : 0;
    }
}

__device__ __forceinline__ int edge_idx(const void* ei, int row, int i) {
    if (g_is64) return (int)((const long long*)ei)[(size_t)row * EE + i];
    return ((const int*)ei)[(size_t)row * EE + i];
}

// ---------------- CSR build ----------------
__global__ void k_deg_init() {
    int i = blockIdx.x * blockDim.x + threadIdx.x;
    if (i < NN) g_deg[i] = 1;   // self-loop counted up-front
}

__global__ void k_deg_count(const void* __restrict__ ei) {
    int i = blockIdx.x * blockDim.x + threadIdx.x;
    if (i < EE) atomicAdd(&g_deg[edge_idx(ei, 1, i)], 1);
}

__global__ void k_scan_block() {
    __shared__ int sh[1024];
    int i = blockIdx.x * 1024 + threadIdx.x;
    int v = (i < NN) ? g_deg[i] : 0;
    sh[threadIdx.x] = v;
    #pragma unroll
    for (int off = 1; off < 1024; off <<= 1) {
        __syncthreads();
        int x = (threadIdx.x >= off) ? sh[threadIdx.x - off] : 0;
        __syncthreads();
        sh[threadIdx.x] += x;
    }
    if (i < NN) g_rowptr[i] = sh[threadIdx.x] - v;         // exclusive
    if (threadIdx.x == 1023) g_bsums[blockIdx.x] = sh[1023];
}

__global__ void k_scan_sums() {
    __shared__ int sh[128];
    int t = threadIdx.x;
    int v = (t < NB) ? g_bsums[t] : 0;
    sh[t] = v;
    #pragma unroll
    for (int off = 1; off < 128; off <<= 1) {
        __syncthreads();
        int x = (t >= off) ? sh[t - off] : 0;
        __syncthreads();
        sh[t] += x;
    }
    if (t < NB) g_bsums[t] = sh[t] - v;                     // exclusive
}

__global__ void k_scan_add() {
    int i = blockIdx.x * 1024 + threadIdx.x;
    if (i < NN) {
        int r = g_rowptr[i] + g_bsums[blockIdx.x];
        g_rowptr[i] = r;
        g_cursor[i] = r;
    }
    if (i == 0) g_rowptr[NN] = ET;
}

__global__ void k_scatter(const void* __restrict__ ei) {
    int i = blockIdx.x * blockDim.x + threadIdx.x;
    if (i >= ET) return;
    int s, d;
    if (i < EE) { s = edge_idx(ei, 0, i); d = edge_idx(ei, 1, i); }
    else        { s = d = i - EE; }
    int pos = atomicAdd(&g_cursor[d], 1);
    g_adj[pos] = s;
}

// ---------------- GEMM1: xh1 = x[N,128] @ W1[128,256] ----------------
__global__ void __launch_bounds__(256) k_gemm1(const float* __restrict__ X,
                                               const float* __restrict__ W) {
    __shared__ float As[16][64];   // As[k][m]
    __shared__ float Bs[16][64];   // Bs[k][n]
    const int bm = blockIdx.x * 64, bn = blockIdx.y * 64;
    const int tid = threadIdx.x;
    const int tm = (tid >> 4) << 2;
    const int tn = (tid & 15) << 2;
    const int lrow = tid >> 2;
    const int lkp  = (tid & 3) << 2;
    const int brow = tid >> 4;
    const int bnp  = (tid & 15) << 2;
    float acc[4][4] = {};
    for (int kt = 0; kt < 128; kt += 16) {
        float4 xv;
        if (bm + lrow < NN)
            xv = *(const float4*)(X + (size_t)(bm + lrow) * 128 + kt + lkp);
        else
            xv = make_float4(0.f, 0.f, 0.f, 0.f);
        As[lkp + 0][lrow] = xv.x; As[lkp + 1][lrow] = xv.y;
        As[lkp + 2][lrow] = xv.z; As[lkp + 3][lrow] = xv.w;
        float4 wv = *(const float4*)(W + (size_t)(kt + brow) * 256 + bn + bnp);
        *(float4*)&Bs[brow][bnp] = wv;
        __syncthreads();
        #pragma unroll
        for (int k = 0; k < 16; k++) {
            float a0 = As[k][tm], a1 = As[k][tm + 1], a2 = As[k][tm + 2], a3 = As[k][tm + 3];
            float b0 = Bs[k][tn], b1 = Bs[k][tn + 1], b2 = Bs[k][tn + 2], b3 = Bs[k][tn + 3];
            acc[0][0] += a0 * b0; acc[0][1] += a0 * b1; acc[0][2] += a0 * b2; acc[0][3] += a0 * b3;
            acc[1][0] += a1 * b0; acc[1][1] += a1 * b1; acc[1][2] += a1 * b2; acc[1][3] += a1 * b3;
            acc[2][0] += a2 * b0; acc[2][1] += a2 * b1; acc[2][2] += a2 * b2; acc[2][3] += a2 * b3;
            acc[3][0] += a3 * b0; acc[3][1] += a3 * b1; acc[3][2] += a3 * b2; acc[3][3] += a3 * b3;
        }
        __syncthreads();
    }
    #pragma unroll
    for (int i = 0; i < 4; i++) {
        int r = bm + tm + i;
        if (r < NN) {
            float4 o = make_float4(acc[i][0], acc[i][1], acc[i][2], acc[i][3]);
            *(float4*)(g_xh1 + (size_t)r * 256 + bn + tn) = o;
        }
    }
}

// ---------------- attention logits layer 1 ----------------
__global__ void k_e1(const float* __restrict__ as1, const float* __restrict__ ad1) {
    int t = blockIdx.x * blockDim.x + threadIdx.x;
    if (t >= NN * 8) return;
    int n = t >> 3, h = t & 7;
    const float4* xp = (const float4*)(g_xh1 + (size_t)n * 256 + h * 32);
    const float4* ap = (const float4*)(as1 + h * 32);
    const float4* dp = (const float4*)(ad1 + h * 32);
    float es = 0.f, ed = 0.f;
    #pragma unroll
    for (int q = 0; q < 8; q++) {
        float4 v = xp[q];
        float4 a = __ldg(&ap[q]);
        float4 d = __ldg(&dp[q]);
        es += v.x * a.x + v.y * a.y + v.z * a.z + v.w * a.w;
        ed += v.x * d.x + v.y * d.y + v.z * d.z + v.w * d.w;
    }
    g_es1[t] = es;
    g_ed1[t] = ed;
}

// ---------------- layer-1 aggregation: warp per dst node ----------------
// out[n] = (sum_e p_e * xh1[src_e]) / (sum_e p_e), p = exp(leaky(es[src]+ed[n]))
// Max-shift of the softmax is skipped: |e| <= ~6 here, exp cannot overflow and
// the normalized result is mathematically identical.
__global__ void k_agg1(const float* __restrict__ b1) {
    int warp = (blockIdx.x * blockDim.x + threadIdx.x) >> 5;
    int lane = threadIdx.x & 31;
    if (warp >= NN) return;
    int n = warp;
    int head = lane >> 2;                 // lane covers channels [lane*8, lane*8+8) -> one head
    float edv = g_ed1[n * 8 + head];
    int s0 = g_rowptr[n], s1 = g_rowptr[n + 1];
    float acc[8] = {0.f, 0.f, 0.f, 0.f, 0.f, 0.f, 0.f, 0.f};
    float s = 0.f;
    for (int k = s0; k < s1; k++) {
        int src = g_adj[k];
        float e = g_es1[src * 8 + head] + edv;
        e = e > 0.f ? e : 0.2f * e;
        float p = __expf(e);
        s += p;
        const float4* xp = (const float4*)(g_xh1 + (size_t)src * 256 + lane * 8);
        float4 v0 = __ldg(&xp[0]);
        float4 v1 = __ldg(&xp[1]);
        acc[0] += p * v0.x; acc[1] += p * v0.y; acc[2] += p * v0.z; acc[3] += p * v0.w;
        acc[4] += p * v1.x; acc[5] += p * v1.y; acc[6] += p * v1.z; acc[7] += p * v1.w;
    }
    float inv = 1.f / (s + 1e-16f);
    size_t base = (size_t)n * 256 + lane * 8;
    float4 o0, o1;
    o0.x = fmaxf(acc[0] * inv + __ldg(&b1[lane * 8 + 0]), 0.f);
    o0.y = fmaxf(acc[1] * inv + __ldg(&b1[lane * 8 + 1]), 0.f);
    o0.z = fmaxf(acc[2] * inv + __ldg(&b1[lane * 8 + 2]), 0.f);
    o0.w = fmaxf(acc[3] * inv + __ldg(&b1[lane * 8 + 3]), 0.f);
    o1.x = fmaxf(acc[4] * inv + __ldg(&b1[lane * 8 + 4]), 0.f);
    o1.y = fmaxf(acc[5] * inv + __ldg(&b1[lane * 8 + 5]), 0.f);
    o1.z = fmaxf(acc[6] * inv + __ldg(&b1[lane * 8 + 6]), 0.f);
    o1.w = fmaxf(acc[7] * inv + __ldg(&b1[lane * 8 + 7]), 0.f);
    *(float4*)(g_h + base) = o0;
    *(float4*)(g_h + base + 4) = o1;
}

// ---------------- GEMM2 + layer-2 logits (fused) ----------------
// xh2 = h[N,256] @ W2[256,32]; es2/ed2 = xh2 . a_{src,dst}2 (warp reduce).
__global__ void __launch_bounds__(256) k_gemm2(const float* __restrict__ W2,
                                               const float* __restrict__ as2,
                                               const float* __restrict__ ad2) {
    __shared__ float Ws[256 * 32];
    __shared__ float rows[8][256];
    int tid = threadIdx.x, warp = tid >> 5, lane = tid & 31;
    for (int i = tid; i < 256 * 32; i += 256) Ws[i] = W2[i];
    int n = blockIdx.x * 8 + warp;
    if (n < NN) {
        const float4* hp = (const float4*)(g_h + (size_t)n * 256);
        float4 v0 = hp[lane * 2], v1 = hp[lane * 2 + 1];
        *(float4*)&rows[warp][lane * 8]     = v0;
        *(float4*)&rows[warp][lane * 8 + 4] = v1;
    }
    __syncthreads();
    if (n >= NN) return;
    float acc = 0.f;
    #pragma unroll 8
    for (int k = 0; k < 256; k++) acc += rows[warp][k] * Ws[k * 32 + lane];
    g_xh2[(size_t)n * 32 + lane] = acc;
    float es = acc * __ldg(&as2[lane]);
    float ed = acc * __ldg(&ad2[lane]);
    #pragma unroll
    for (int off = 16; off > 0; off >>= 1) {
        es += __shfl_xor_sync(0xffffffffu, es, off);
        ed += __shfl_xor_sync(0xffffffffu, ed, off);
    }
    if (lane == 0) { g_es2[n] = es; g_ed2[n] = ed; }
}

// ---------------- layer-2 aggregation: warp per dst node, lane = channel ----
__global__ void k_agg2(float* __restrict__ out, const float* __restrict__ b2) {
    int warp = (blockIdx.x * blockDim.x + threadIdx.x) >> 5;
    int lane = threadIdx.x & 31;
    if (warp >= NN) return;
    int n = warp;
    float edv = g_ed2[n];
    int s0 = g_rowptr[n], s1 = g_rowptr[n + 1];
    float acc = 0.f, s = 0.f;
    for (int k = s0; k < s1; k++) {
        int src = g_adj[k];
        float e = g_es2[src] + edv;
        e = e > 0.f ? e : 0.2f * e;
        float p = __expf(e);
        s += p;
        acc += p * __ldg(&g_xh2[(size_t)src * 32 + lane]);
    }
    out[(size_t)n * 32 + lane] = acc / (s + 1e-16f) + __ldg(&b2[lane]);
}

// ---------------- launch ----------------
extern "C" void kernel_launch(void* const* d_in, const int* in_sizes, int n_in,
                              void* d_out, int out_size) {
    const float* x   = (const float*)d_in[0];
    const void*  ei  = d_in[1];
    const float* W1  = (const float*)d_in[2];
    const float* as1 = (const float*)d_in[3];
    const float* ad1 = (const float*)d_in[4];
    const float* b1  = (const float*)d_in[5];
    const float* W2  = (const float*)d_in[6];
    const float* as2 = (const float*)d_in[7];
    const float* ad2 = (const float*)d_in[8];
    const float* b2  = (const float*)d_in[9];
    float* out = (float*)d_out;

    k_detect<<<1, 32>>>((const int*)ei);
    k_deg_init<<<(NN + 255) / 256, 256>>>();
    k_deg_count<<<(EE + 255) / 256, 256>>>(ei);
    k_scan_block<<<NB, 1024>>>();
    k_scan_sums<<<1, 128>>>();
    k_scan_add<<<NB, 1024>>>();
    k_scatter<<<(ET + 255) / 256, 256>>>(ei);

    k_gemm1<<<dim3((NN + 63) / 64, 4), 256>>>(x, W1);
    k_e1<<<(NN * 8 + 255) / 256, 256>>>(as1, ad1);
    k_agg1<<<NN / 8, 256>>>(b1);

    k_gemm2<<<NN / 8, 256>>>(W2, as2, ad2);
    k_agg2<<<NN / 8, 256>>>(out, b2);
}